// round 13
// baseline (speedup 1.0000x reference)
#include <cuda_runtime.h>
#include <cstdint>

#define Bb    16
#define H4    4096
#define KC    256           // k-rows per block
#define NKC   4             // k-chunks per matrix
#define NSPLIT 8            // NKC * 2 matrices
#define TPB   256
#define COLS  256           // columns per block (1 per thread)
#define SK    16            // k-rows per stage (16 KB)
#define NST   (KC / SK)     // 16 stages
#define RS    8             // ring slots (128 KB)
#define ROW_BYTES   (COLS * 4)          // 1 KB
#define STAGE_BYTES (SK * ROW_BYTES)    // 16 KB
#define SMEM_BYTES  (RS * SK * COLS * 4 + KC * Bb * 4 + RS * 8)

// scratch: 64 float2-planes of [H4]; plane p = sp*8 + q holds {b=2q, b=2q+1}
__device__ float g_part[(size_t)NSPLIT * Bb * H4];   // 2 MB

__device__ __forceinline__ unsigned long long pack2(float lo, float hi) {
    unsigned long long r;
    asm("mov.b64 %0, {%1, %2};" : "=l"(r) : "f"(lo), "f"(hi));
    return r;
}
__device__ __forceinline__ unsigned long long fma2(unsigned long long a,
                                                   unsigned long long b,
                                                   unsigned long long c) {
    unsigned long long d;
    asm("fma.rn.f32x2 %0, %1, %2, %3;" : "=l"(d) : "l"(a), "l"(b), "l"(c));
    return d;
}
__device__ __forceinline__ uint32_t smem_u32(const void* p) {
    uint32_t a;
    asm("{ .reg .u64 t; cvta.to.shared.u64 t, %1; cvt.u32.u64 %0, t; }"
        : "=r"(a) : "l"(p));
    return a;
}
__device__ __forceinline__ void mbar_init(uint32_t mbar, uint32_t cnt) {
    asm volatile("mbarrier.init.shared.b64 [%0], %1;" :: "r"(mbar), "r"(cnt) : "memory");
}
__device__ __forceinline__ void mbar_expect_tx(uint32_t mbar, uint32_t bytes) {
    asm volatile("mbarrier.arrive.expect_tx.shared.b64 _, [%0], %1;"
                 :: "r"(mbar), "r"(bytes) : "memory");
}
__device__ __forceinline__ void mbar_wait(uint32_t mbar, uint32_t phase) {
    asm volatile(
        "{\n\t.reg .pred P;\n\t"
        "W_%=:\n\t"
        "mbarrier.try_wait.parity.acquire.cta.shared::cta.b64 P, [%0], %1, 0x989680;\n\t"
        "@P bra D_%=;\n\t"
        "bra W_%=;\n\t"
        "D_%=:\n\t}"
        :: "r"(mbar), "r"(phase) : "memory");
}
__device__ __forceinline__ void bulk_copy(uint32_t dst_smem, const void* src,
                                          uint32_t bytes, uint32_t mbar) {
    asm volatile(
        "cp.async.bulk.shared::cluster.global.mbarrier::complete_tx::bytes "
        "[%0], [%1], %2, [%3];"
        :: "r"(dst_smem), "l"(src), "r"(bytes), "r"(mbar) : "memory");
}

// ---------------------------------------------------------------------------
// Kernel 1: split-K GEMM partials.
// grid = (16 j-tiles, 4 k-chunks, 2 matrices) = 128 blocks, 256 threads.
// Ring: 8 x 16KB TMA stages (128KB in flight / block).
// Per thread: 1 col x 16 batches = 8 f32x2 accumulators; per k-row:
// 1 LDS.32 (weight) + 4 broadcast LDS.128 (acts) + 8 FFMA2.
// ---------------------------------------------------------------------------
__global__ __launch_bounds__(TPB, 1) void gemm_part(
    const float* __restrict__ Wi, const float* __restrict__ Wh,
    const float* __restrict__ x,  const float* __restrict__ h)
{
    extern __shared__ char dsm[];
    float* wsm    = reinterpret_cast<float*>(dsm);            // RS*SK*COLS
    float* sh_act = wsm + RS * SK * COLS;                     // KC*Bb
    unsigned long long* mbar =
        reinterpret_cast<unsigned long long*>(sh_act + KC * Bb);

    const int jt  = blockIdx.x;            // 0..15
    const int kc  = blockIdx.y;            // 0..3
    const int mat = blockIdx.z;            // 0: Wi/x, 1: Wh/h
    const float* __restrict__ W   = mat ? Wh : Wi;
    const float* __restrict__ act = mat ? h  : x;
    const int k0  = kc * KC;
    const int tid = threadIdx.x;

    uint32_t mb[RS];
#pragma unroll
    for (int i = 0; i < RS; i++) mb[i] = smem_u32(&mbar[i]);
    const uint32_t wbase = smem_u32(wsm);
    const float* Wbase = W + (size_t)k0 * H4 + jt * COLS;

    if (tid == 0) {
#pragma unroll
        for (int i = 0; i < RS; i++) mbar_init(mb[i], 1);
    }

    // stage activations [k][b]
    for (int i = tid; i < Bb * KC; i += TPB) {
        int b = i >> 8;          // i / KC
        int k = i & (KC - 1);
        sh_act[k * Bb + b] = act[b * 1024 + k0 + k];
    }
    __syncthreads();   // orders mbar_init before waits; acts visible

    // prologue: fill the whole ring (8 x 16KB = 128 KB in flight)
    if (tid == 0) {
#pragma unroll
        for (int st = 0; st < RS; st++) {
            mbar_expect_tx(mb[st], STAGE_BYTES);
#pragma unroll
            for (int r = 0; r < SK; r++)
                bulk_copy(wbase + (st * SK + r) * ROW_BYTES,
                          Wbase + (size_t)(st * SK + r) * H4, ROW_BYTES, mb[st]);
        }
    }

    unsigned long long acc[8];             // batch-pairs for this column
#pragma unroll
    for (int q = 0; q < 8; q++) acc[q] = 0ull;

    for (int s = 0; s < NST; s++) {
        const int slot = s & (RS - 1);
        mbar_wait(mb[slot], (s >> 3) & 1);
        const float* wst = wsm + slot * SK * COLS;

#pragma unroll
        for (int r = 0; r < SK; r++) {
            const int k = s * SK + r;
            float w = wst[r * COLS + tid];
            const float* ak = &sh_act[k * Bb];
            ulonglong2 A0 = *reinterpret_cast<const ulonglong2*>(ak);
            ulonglong2 A1 = *reinterpret_cast<const ulonglong2*>(ak + 4);
            ulonglong2 A2 = *reinterpret_cast<const ulonglong2*>(ak + 8);
            ulonglong2 A3 = *reinterpret_cast<const ulonglong2*>(ak + 12);
            unsigned long long wv = pack2(w, w);
            acc[0] = fma2(wv, A0.x, acc[0]);
            acc[1] = fma2(wv, A0.y, acc[1]);
            acc[2] = fma2(wv, A1.x, acc[2]);
            acc[3] = fma2(wv, A1.y, acc[3]);
            acc[4] = fma2(wv, A2.x, acc[4]);
            acc[5] = fma2(wv, A2.y, acc[5]);
            acc[6] = fma2(wv, A3.x, acc[6]);
            acc[7] = fma2(wv, A3.y, acc[7]);
        }

        // refill this slot with stage s+RS (first 8 stages only)
        if (s + RS < NST) {
            __syncthreads();
            if (tid == 0) {
                mbar_expect_tx(mb[slot], STAGE_BYTES);
#pragma unroll
                for (int r = 0; r < SK; r++)
                    bulk_copy(wbase + (slot * SK + r) * ROW_BYTES,
                              Wbase + (size_t)((s + RS) * SK + r) * H4,
                              ROW_BYTES, mb[slot]);
            }
        }
    }

    // epilogue: STG.64 into per-(split, q) float2 planes
    const int sp = mat * NKC + kc;         // 0..7
    const int j0 = jt * COLS + tid;
#pragma unroll
    for (int q = 0; q < 8; q++) {
        unsigned long long* plane =
            reinterpret_cast<unsigned long long*>(g_part) + (size_t)(sp * 8 + q) * H4;
        plane[j0] = acc[q];
    }
}

// ---------------------------------------------------------------------------
// Kernel 2 (fused): reduce 8 partials + biases + LSTM gates -> out.
// grid = 256 blocks x 128 threads; block = (q = bid&7, nc = bid>>3).
// Phase 1: thread (g, nl) sums 8 splits (register-batched) + bias -> smem.
// Phase 2: 64 threads apply gates for batches 2q, 2q+1 over 32 columns.
// out = [h_new (B*H) | c_new (B*H)]
// ---------------------------------------------------------------------------
__global__ __launch_bounds__(128, 1) void reduce_gates(
    const float* __restrict__ Wib, const float* __restrict__ Whb,
    const float* __restrict__ c,   float* __restrict__ out)
{
    __shared__ float2 sg[4][32];

    const int bid = blockIdx.x;        // 0..255
    const int q   = bid & 7;
    const int nc  = bid >> 3;          // 0..31
    const int tid = threadIdx.x;
    const int g   = tid >> 5;          // gate 0..3
    const int nl  = tid & 31;
    const int n   = nc * 32 + nl;

    const float2* gp = reinterpret_cast<const float2*>(g_part)
                     + (size_t)q * H4 + g * 1024 + n;
    float2 t[NSPLIT];
#pragma unroll
    for (int i = 0; i < NSPLIT; i++)
        t[i] = gp[(size_t)(i * 8) * H4];
    float sx = 0.f, sy = 0.f;
#pragma unroll
    for (int i = 0; i < NSPLIT; i++) { sx += t[i].x; sy += t[i].y; }

    float bias = Wib[g * 1024 + n] + Whb[g * 1024 + n];
    sg[g][nl] = make_float2(sx + bias, sy + bias);
    __syncthreads();

    if (tid < 64) {
        const int bl  = tid >> 5;      // 0/1 within batch-pair
        const int nl2 = tid & 31;
        const int n2  = nc * 32 + nl2;
        const int b   = 2 * q + bl;
        float iv = bl ? sg[0][nl2].y : sg[0][nl2].x;
        float fv = bl ? sg[1][nl2].y : sg[1][nl2].x;
        float gv = bl ? sg[2][nl2].y : sg[2][nl2].x;
        float ov = bl ? sg[3][nl2].y : sg[3][nl2].x;
        float ig = 1.0f / (1.0f + expf(-iv));
        float fg = 1.0f / (1.0f + expf(-fv));
        float gg = tanhf(gv);
        float og = 1.0f / (1.0f + expf(-ov));
        float cn = fg * c[b * 1024 + n2] + ig * gg;
        out[b * 1024 + n2] = og * tanhf(cn);
        out[Bb * 1024 + b * 1024 + n2] = cn;
    }
}

// ---------------------------------------------------------------------------
// Inputs (metadata order): x, h, c, context, Wi, Wi_b, Wh, Wh_b, AZ_il, AZ_ir,
// AZ_hl, AZ_hr.  context / AZ_* are dead (multiplied by 0 in the reference).
// ---------------------------------------------------------------------------
extern "C" void kernel_launch(void* const* d_in, const int* in_sizes, int n_in,
                              void* d_out, int out_size)
{
    (void)in_sizes; (void)n_in; (void)out_size;
    const float* x   = (const float*)d_in[0];
    const float* h   = (const float*)d_in[1];
    const float* c   = (const float*)d_in[2];
    const float* Wi  = (const float*)d_in[4];
    const float* Wib = (const float*)d_in[5];
    const float* Wh  = (const float*)d_in[6];
    const float* Whb = (const float*)d_in[7];
    float* out = (float*)d_out;

    cudaFuncSetAttribute(gemm_part,
                         cudaFuncAttributeMaxDynamicSharedMemorySize,
                         SMEM_BYTES);

    dim3 g1(16, NKC, 2);
    gemm_part<<<g1, TPB, SMEM_BYTES>>>(Wi, Wh, x, h);
    reduce_gates<<<256, 128>>>(Wib, Whb, c, out);
}

// round 14
// speedup vs baseline: 1.3130x; 1.3130x over previous
#include <cuda_runtime.h>
#include <cstdint>

#define Bb    16
#define H4    4096
#define KC    128           // k-rows per block
#define NKC   8             // k-chunks per matrix
#define NSPLIT 16           // NKC * 2 matrices
#define TPB   256
#define COLS  512           // columns per block (2 per thread)
#define SK    8             // k-rows per stage (16 KB)
#define NST   (KC / SK)     // 16 stages
#define RS    8             // ring slots (128 KB)
#define NBLK  128
#define ROW_BYTES   (COLS * 4)          // 2 KB
#define STAGE_BYTES (SK * ROW_BYTES)    // 16 KB
#define SMEM_BYTES  (RS * SK * COLS * 4 + KC * Bb * 4 + RS * 8)

// scratch: 128 float2-planes of [H4]; plane p = sp*8 + q holds {b=2q, b=2q+1}
__device__ float g_part[(size_t)NSPLIT * Bb * H4];   // 4 MB
__device__ int   g_c1;                                // grid-barrier arrive
__device__ int   g_c2;                                // grid-barrier depart

__device__ __forceinline__ unsigned long long pack2(float lo, float hi) {
    unsigned long long r;
    asm("mov.b64 %0, {%1, %2};" : "=l"(r) : "f"(lo), "f"(hi));
    return r;
}
__device__ __forceinline__ unsigned long long fma2(unsigned long long a,
                                                   unsigned long long b,
                                                   unsigned long long c) {
    unsigned long long d;
    asm("fma.rn.f32x2 %0, %1, %2, %3;" : "=l"(d) : "l"(a), "l"(b), "l"(c));
    return d;
}
__device__ __forceinline__ uint32_t smem_u32(const void* p) {
    uint32_t a;
    asm("{ .reg .u64 t; cvta.to.shared.u64 t, %1; cvt.u32.u64 %0, t; }"
        : "=r"(a) : "l"(p));
    return a;
}
__device__ __forceinline__ void mbar_init(uint32_t mbar, uint32_t cnt) {
    asm volatile("mbarrier.init.shared.b64 [%0], %1;" :: "r"(mbar), "r"(cnt) : "memory");
}
__device__ __forceinline__ void mbar_expect_tx(uint32_t mbar, uint32_t bytes) {
    asm volatile("mbarrier.arrive.expect_tx.shared.b64 _, [%0], %1;"
                 :: "r"(mbar), "r"(bytes) : "memory");
}
__device__ __forceinline__ void mbar_wait(uint32_t mbar, uint32_t phase) {
    asm volatile(
        "{\n\t.reg .pred P;\n\t"
        "W_%=:\n\t"
        "mbarrier.try_wait.parity.acquire.cta.shared::cta.b64 P, [%0], %1, 0x989680;\n\t"
        "@P bra D_%=;\n\t"
        "bra W_%=;\n\t"
        "D_%=:\n\t}"
        :: "r"(mbar), "r"(phase) : "memory");
}
__device__ __forceinline__ void bulk_copy(uint32_t dst_smem, const void* src,
                                          uint32_t bytes, uint32_t mbar) {
    asm volatile(
        "cp.async.bulk.shared::cluster.global.mbarrier::complete_tx::bytes "
        "[%0], [%1], %2, [%3];"
        :: "r"(dst_smem), "l"(src), "r"(bytes), "r"(mbar) : "memory");
}

// ---------------------------------------------------------------------------
// Fused kernel: split-K GEMM -> grid barrier -> reduce + gates.
// grid = 128 blocks (1/SM, single wave: barrier is deadlock-free), 256 thr.
// Phase A: bid -> (jt = bid&7, kc = (bid>>3)&7, mat = bid>>6).
//   Ring of 8 x 16KB TMA stages; per thread 2 cols x 16 batches, per k-row:
//   1 LDS.64 (w) + 4 broadcast LDS.128 (acts) + 16 FFMA2.
// Barrier: two-counter arrive/reset (self-resetting for graph replay).
// Phase B: block handles 64 (q,n) items; thread (g, item) sums 16 splits
//   (L2-resident float2) + bias -> smem; 128 threads apply LSTM gates.
// out = [h_new (B*H) | c_new (B*H)]
// ---------------------------------------------------------------------------
__global__ __launch_bounds__(TPB, 1) void lstm_fused(
    const float* __restrict__ Wi,  const float* __restrict__ Wh,
    const float* __restrict__ x,   const float* __restrict__ h,
    const float* __restrict__ Wib, const float* __restrict__ Whb,
    const float* __restrict__ c,   float* __restrict__ out)
{
    extern __shared__ char dsm[];
    float* wsm    = reinterpret_cast<float*>(dsm);            // RS*SK*COLS
    float* sh_act = wsm + RS * SK * COLS;                     // KC*Bb
    unsigned long long* mbar =
        reinterpret_cast<unsigned long long*>(sh_act + KC * Bb);

    const int bid = blockIdx.x;            // 0..127
    const int jt  = bid & 7;
    const int kc  = (bid >> 3) & 7;
    const int mat = bid >> 6;              // 0: Wi/x, 1: Wh/h
    const float* __restrict__ W   = mat ? Wh : Wi;
    const float* __restrict__ act = mat ? h  : x;
    const int k0  = kc * KC;
    const int tid = threadIdx.x;

    uint32_t mb[RS];
#pragma unroll
    for (int i = 0; i < RS; i++) mb[i] = smem_u32(&mbar[i]);
    const uint32_t wbase = smem_u32(wsm);
    const float* Wbase = W + (size_t)k0 * H4 + jt * COLS;

    if (tid == 0) {
#pragma unroll
        for (int i = 0; i < RS; i++) mbar_init(mb[i], 1);
    }

    // stage activations [k][b]
    for (int i = tid; i < Bb * KC; i += TPB) {
        int b = i >> 7;
        int k = i & (KC - 1);
        sh_act[k * Bb + b] = act[b * 1024 + k0 + k];
    }
    __syncthreads();   // orders mbar_init before waits; acts visible

    // prologue: fill the whole ring (8 x 16KB = 128 KB in flight)
    if (tid == 0) {
#pragma unroll
        for (int st = 0; st < RS; st++) {
            mbar_expect_tx(mb[st], STAGE_BYTES);
#pragma unroll
            for (int r = 0; r < SK; r++)
                bulk_copy(wbase + (st * SK + r) * ROW_BYTES,
                          Wbase + (size_t)(st * SK + r) * H4, ROW_BYTES, mb[st]);
        }
    }

    unsigned long long acc[2][8];          // [col][batch-pair]
#pragma unroll
    for (int cc = 0; cc < 2; cc++)
#pragma unroll
        for (int q = 0; q < 8; q++) acc[cc][q] = 0ull;

    for (int s = 0; s < NST; s++) {
        const int slot = s & (RS - 1);
        mbar_wait(mb[slot], (s >> 3) & 1);
        const float* wst = wsm + slot * SK * COLS;

#pragma unroll
        for (int r = 0; r < SK; r++) {
            const int k = s * SK + r;
            float2 w = *reinterpret_cast<const float2*>(&wst[r * COLS + tid * 2]);
            const float* ak = &sh_act[k * Bb];
            ulonglong2 A0 = *reinterpret_cast<const ulonglong2*>(ak);
            ulonglong2 A1 = *reinterpret_cast<const ulonglong2*>(ak + 4);
            ulonglong2 A2 = *reinterpret_cast<const ulonglong2*>(ak + 8);
            ulonglong2 A3 = *reinterpret_cast<const ulonglong2*>(ak + 12);
            unsigned long long w0 = pack2(w.x, w.x);
            unsigned long long w1 = pack2(w.y, w.y);
            acc[0][0] = fma2(w0, A0.x, acc[0][0]);
            acc[0][1] = fma2(w0, A0.y, acc[0][1]);
            acc[0][2] = fma2(w0, A1.x, acc[0][2]);
            acc[0][3] = fma2(w0, A1.y, acc[0][3]);
            acc[0][4] = fma2(w0, A2.x, acc[0][4]);
            acc[0][5] = fma2(w0, A2.y, acc[0][5]);
            acc[0][6] = fma2(w0, A3.x, acc[0][6]);
            acc[0][7] = fma2(w0, A3.y, acc[0][7]);
            acc[1][0] = fma2(w1, A0.x, acc[1][0]);
            acc[1][1] = fma2(w1, A0.y, acc[1][1]);
            acc[1][2] = fma2(w1, A1.x, acc[1][2]);
            acc[1][3] = fma2(w1, A1.y, acc[1][3]);
            acc[1][4] = fma2(w1, A2.x, acc[1][4]);
            acc[1][5] = fma2(w1, A2.y, acc[1][5]);
            acc[1][6] = fma2(w1, A3.x, acc[1][6]);
            acc[1][7] = fma2(w1, A3.y, acc[1][7]);
        }

        if (s + RS < NST) {
            __syncthreads();
            if (tid == 0) {
                mbar_expect_tx(mb[slot], STAGE_BYTES);
#pragma unroll
                for (int r = 0; r < SK; r++)
                    bulk_copy(wbase + (slot * SK + r) * ROW_BYTES,
                              Wbase + (size_t)((s + RS) * SK + r) * H4,
                              ROW_BYTES, mb[slot]);
            }
        }
    }

    // epilogue: STG.128 partials into per-(split, q) float2 planes
    const int sp = mat * NKC + kc;         // 0..15
    const int j0 = jt * COLS + tid * 2;
#pragma unroll
    for (int q = 0; q < 8; q++) {
        float2* plane = reinterpret_cast<float2*>(g_part) + (size_t)(sp * 8 + q) * H4;
        *reinterpret_cast<ulonglong2*>(plane + j0) =
            make_ulonglong2(acc[0][q], acc[1][q]);
    }

    // ---- grid barrier (all 128 blocks co-resident: 1 block/SM, 1 wave) ----
    __threadfence();                       // publish partials
    __syncthreads();
    __shared__ int s_reset;
    if (tid == 0) {
        int old = atomicAdd(&g_c1, 1);
        s_reset = (old == 0);              // exactly one resetter per launch
        while (atomicAdd(&g_c1, 0) < NBLK) __nanosleep(64);
        __threadfence();                   // acquire partials from all blocks
        atomicAdd(&g_c2, 1);
    }
    __syncthreads();

    // ---- Phase B: reduce 16 splits + bias + gates for 64 items ----
    {
        float2* sg = reinterpret_cast<float2*>(dsm);   // [4][64], wsm done
        const int il = tid & 63;
        const int g  = tid >> 6;           // gate 0..3
        const int m  = bid * 64 + il;      // 0..8191
        const int q  = m >> 10;
        const int n  = m & 1023;

        const float2* gp = reinterpret_cast<const float2*>(g_part)
                         + (size_t)q * H4 + g * 1024 + n;
        float2 t[NSPLIT];
#pragma unroll
        for (int i = 0; i < NSPLIT; i++)
            t[i] = gp[(size_t)(i * 8) * H4];
        float sx = 0.f, sy = 0.f;
#pragma unroll
        for (int i = 0; i < NSPLIT; i++) { sx += t[i].x; sy += t[i].y; }
        float bias = Wib[g * 1024 + n] + Whb[g * 1024 + n];
        sg[g * 64 + il] = make_float2(sx + bias, sy + bias);
        __syncthreads();

        if (tid < 128) {
            const int bl  = tid >> 6;      // 0/1 within batch-pair
            const int il2 = tid & 63;
            const int m2  = bid * 64 + il2;
            const int q2  = m2 >> 10;
            const int n2  = m2 & 1023;
            const int b   = 2 * q2 + bl;
            float iv = bl ? sg[0 * 64 + il2].y : sg[0 * 64 + il2].x;
            float fv = bl ? sg[1 * 64 + il2].y : sg[1 * 64 + il2].x;
            float gv = bl ? sg[2 * 64 + il2].y : sg[2 * 64 + il2].x;
            float ov = bl ? sg[3 * 64 + il2].y : sg[3 * 64 + il2].x;
            float ig = 1.0f / (1.0f + expf(-iv));
            float fg = 1.0f / (1.0f + expf(-fv));
            float gg = tanhf(gv);
            float og = 1.0f / (1.0f + expf(-ov));
            float cn = fg * c[b * 1024 + n2] + ig * gg;
            out[b * 1024 + n2] = og * tanhf(cn);
            out[Bb * 1024 + b * 1024 + n2] = cn;
        }
        __syncthreads();
    }

    // resetter: restore counters for the next graph replay
    if (tid == 0 && s_reset) {
        while (atomicAdd(&g_c2, 0) < NBLK) __nanosleep(64);
        atomicExch(&g_c1, 0);
        atomicExch(&g_c2, 0);
    }
}

// ---------------------------------------------------------------------------
// Inputs (metadata order): x, h, c, context, Wi, Wi_b, Wh, Wh_b, AZ_il, AZ_ir,
// AZ_hl, AZ_hr.  context / AZ_* are dead (multiplied by 0 in the reference).
// ---------------------------------------------------------------------------
extern "C" void kernel_launch(void* const* d_in, const int* in_sizes, int n_in,
                              void* d_out, int out_size)
{
    (void)in_sizes; (void)n_in; (void)out_size;
    const float* x   = (const float*)d_in[0];
    const float* h   = (const float*)d_in[1];
    const float* c   = (const float*)d_in[2];
    const float* Wi  = (const float*)d_in[4];
    const float* Wib = (const float*)d_in[5];
    const float* Wh  = (const float*)d_in[6];
    const float* Whb = (const float*)d_in[7];
    float* out = (float*)d_out;

    cudaFuncSetAttribute(lstm_fused,
                         cudaFuncAttributeMaxDynamicSharedMemorySize,
                         SMEM_BYTES);

    lstm_fused<<<NBLK, TPB, SMEM_BYTES>>>(Wi, Wh, x, h, Wib, Whb, c, out);
}